// round 3
// baseline (speedup 1.0000x reference)
#include <cuda_runtime.h>
#include <cstdint>
#include <cstddef>

#define N_NODES   50000
#define N_EDGES   800000
#define E_TOT     850000   // edges + self loops
#define NEG_SLOPE 0.2f

// ---------------------------------------------------------------------------
// Static device scratch (allocation-free; ~167 MB)
// ---------------------------------------------------------------------------
static __device__ __align__(256) float g_h  [(size_t)N_NODES * 256];  // layer io
static __device__ __align__(256) float g_xp [(size_t)N_NODES * 256];  // x @ W
static __device__ __align__(256) float g_acc[(size_t)N_NODES * 256];  // scatter accum
static __device__ __align__(256) float g_s  [N_NODES * 4];
static __device__ __align__(256) float g_d  [N_NODES * 4];
static __device__ __align__(256) float g_emax[N_NODES * 4];
static __device__ __align__(256) float g_den [N_NODES * 4];
static __device__ __align__(256) float g_ee [(size_t)E_TOT * 4];

// ---------------------------------------------------------------------------
// Helpers
// ---------------------------------------------------------------------------
__device__ __forceinline__ void atomicMaxFloat(float* addr, float value) {
    // int/uint ordering trick; correct for all finite floats with -inf init
    if (value >= 0.f)
        atomicMax((int*)addr, __float_as_int(value));
    else
        atomicMin((unsigned int*)addr, __float_as_uint(value));
}

__device__ __forceinline__ void red_add_v4(float* p, float x, float y, float z, float w) {
    asm volatile("red.global.add.v4.f32 [%0], {%1, %2, %3, %4};"
                 :: "l"(p), "f"(x), "f"(y), "f"(z), "f"(w) : "memory");
}

__device__ __forceinline__ float lrelu(float v) {
    return v > 0.f ? v : NEG_SLOPE * v;
}

// ---------------------------------------------------------------------------
// SGEMM: C[M,N] = A[M,K] @ B[K,N], row-major, fp32.
// BM=BN=128, BK=16, 256 threads, TM=TN=8, double-buffered smem with
// register-staged global prefetch. K must be a multiple of 16 (128/256 here).
// Row guard on A/C (M=50000), col guard on B/C (layer 3 has N=64 < BN).
// ---------------------------------------------------------------------------
__global__ __launch_bounds__(256)
void sgemm_kernel(const float* __restrict__ A, const float* __restrict__ B,
                  float* __restrict__ C, int M, int N, int K)
{
    constexpr int BM = 128, BN = 128, BK = 16, TM = 8, TN = 8;
    __shared__ float As[2][BK][BM];
    __shared__ float Bs[2][BK][BN];

    const int tid = threadIdx.x;
    const int tx = tid % (BN / TN);          // 0..15
    const int ty = tid / (BN / TN);          // 0..15
    const int rowBase = blockIdx.x * BM;
    const int colBase = blockIdx.y * BN;

    // A tile: 128 rows x 16 cols = 512 float4; 2 per thread (rows r, r+64)
    const int aRow = tid / 4;                // 0..63
    const int aCol = (tid % 4) * 4;          // 0,4,8,12
    // B tile: 16 rows x 128 cols = 512 float4; 2 per thread (rows r, r+8)
    const int bRow = tid / 32;               // 0..7
    const int bCol = (tid % 32) * 4;         // 0..124

    float acc[TM][TN];
#pragma unroll
    for (int i = 0; i < TM; i++)
#pragma unroll
        for (int j = 0; j < TN; j++) acc[i][j] = 0.f;

    const bool bColOk = (colBase + bCol) < N;

    // ---- preload tile 0 into buffer 0 ----
    {
        float4 a0 = make_float4(0.f,0.f,0.f,0.f), a1 = a0, b0 = a0, b1 = a0;
        int gr0 = rowBase + aRow, gr1 = gr0 + 64;
        if (gr0 < M) a0 = *(const float4*)&A[(size_t)gr0 * K + aCol];
        if (gr1 < M) a1 = *(const float4*)&A[(size_t)gr1 * K + aCol];
        if (bColOk) {
            b0 = *(const float4*)&B[(size_t)(bRow    ) * N + colBase + bCol];
            b1 = *(const float4*)&B[(size_t)(bRow + 8) * N + colBase + bCol];
        }
        As[0][aCol+0][aRow] = a0.x; As[0][aCol+1][aRow] = a0.y;
        As[0][aCol+2][aRow] = a0.z; As[0][aCol+3][aRow] = a0.w;
        As[0][aCol+0][aRow+64] = a1.x; As[0][aCol+1][aRow+64] = a1.y;
        As[0][aCol+2][aRow+64] = a1.z; As[0][aCol+3][aRow+64] = a1.w;
        *(float4*)&Bs[0][bRow    ][bCol] = b0;
        *(float4*)&Bs[0][bRow + 8][bCol] = b1;
    }
    __syncthreads();

    int buf = 0;
    for (int k0 = 0; k0 < K; k0 += BK) {
        float4 a0, a1, b0, b1;
        const bool hasNext = (k0 + BK) < K;
        if (hasNext) {
            a0 = make_float4(0.f,0.f,0.f,0.f); a1 = a0; b0 = a0; b1 = a0;
            int kn = k0 + BK;
            int gr0 = rowBase + aRow, gr1 = gr0 + 64;
            if (gr0 < M) a0 = *(const float4*)&A[(size_t)gr0 * K + kn + aCol];
            if (gr1 < M) a1 = *(const float4*)&A[(size_t)gr1 * K + kn + aCol];
            if (bColOk) {
                b0 = *(const float4*)&B[(size_t)(kn + bRow    ) * N + colBase + bCol];
                b1 = *(const float4*)&B[(size_t)(kn + bRow + 8) * N + colBase + bCol];
            }
        }

#pragma unroll
        for (int k = 0; k < BK; k++) {
            float ra[TM], rb[TN];
#pragma unroll
            for (int i = 0; i < TM; i++) ra[i] = As[buf][k][ty * TM + i];
#pragma unroll
            for (int j = 0; j < TN; j++) rb[j] = Bs[buf][k][tx * TN + j];
#pragma unroll
            for (int i = 0; i < TM; i++)
#pragma unroll
                for (int j = 0; j < TN; j++)
                    acc[i][j] = fmaf(ra[i], rb[j], acc[i][j]);
        }

        if (hasNext) {
            int nb = buf ^ 1;
            As[nb][aCol+0][aRow] = a0.x; As[nb][aCol+1][aRow] = a0.y;
            As[nb][aCol+2][aRow] = a0.z; As[nb][aCol+3][aRow] = a0.w;
            As[nb][aCol+0][aRow+64] = a1.x; As[nb][aCol+1][aRow+64] = a1.y;
            As[nb][aCol+2][aRow+64] = a1.z; As[nb][aCol+3][aRow+64] = a1.w;
            *(float4*)&Bs[nb][bRow    ][bCol] = b0;
            *(float4*)&Bs[nb][bRow + 8][bCol] = b1;
            __syncthreads();
            buf = nb;
        }
    }

#pragma unroll
    for (int i = 0; i < TM; i++) {
        int gr = rowBase + ty * TM + i;
        if (gr >= M) continue;
        int gc = colBase + tx * TN;
        if (gc >= N) continue;   // N is a multiple of 8, so gc<N => gc+7<N
#pragma unroll
        for (int j = 0; j < TN; j += 4) {
            float4 v = make_float4(acc[i][j], acc[i][j+1], acc[i][j+2], acc[i][j+3]);
            *(float4*)&C[(size_t)gr * N + gc + j] = v;
        }
    }
}

// ---------------------------------------------------------------------------
// s[n,h] = <xp[n,h,:], a_src[h,:]>, d[n,h] = <xp[n,h,:], a_dst[h,:]>
// one warp per (n,h)
// ---------------------------------------------------------------------------
__global__ void sd_kernel(const float* __restrict__ xp,
                          const float* __restrict__ asrc, const float* __restrict__ adst,
                          float* __restrict__ s, float* __restrict__ d,
                          int H, int C)
{
    int wid  = (blockIdx.x * blockDim.x + threadIdx.x) >> 5;
    int lane = threadIdx.x & 31;
    if (wid >= N_NODES * H) return;
    int n = wid / H, h = wid % H;
    const float* row = xp + (size_t)n * H * C + (size_t)h * C;
    float vs = 0.f, vd = 0.f;
    for (int c = lane; c < C; c += 32) {
        float v = row[c];
        vs = fmaf(v, asrc[h * C + c], vs);
        vd = fmaf(v, adst[h * C + c], vd);
    }
#pragma unroll
    for (int o = 16; o; o >>= 1) {
        vs += __shfl_down_sync(0xffffffffu, vs, o);
        vd += __shfl_down_sync(0xffffffffu, vd, o);
    }
    if (lane == 0) { s[wid] = vs; d[wid] = vd; }
}

// ---------------------------------------------------------------------------
// fused init: emax = -inf, den = 0, acc = 0
// ---------------------------------------------------------------------------
__global__ void init_layer_kernel(float* __restrict__ emax, float* __restrict__ den,
                                  int nh, float* __restrict__ acc, long long nacc)
{
    long long i = (long long)blockIdx.x * blockDim.x + threadIdx.x;
    long long stride = (long long)gridDim.x * blockDim.x;
    if (i < nh) { emax[i] = __int_as_float(0xff800000); den[i] = 0.f; }
    for (long long j = i; j < nacc; j += stride) acc[j] = 0.f;
}

// ---------------------------------------------------------------------------
// edge pass 1: e = leaky_relu(s[src]+d[dst]); segment-max into emax
// (e not stored: pass 2 recomputes from L2-resident s/d)
// ---------------------------------------------------------------------------
template<int H>
__global__ void edge_pass1_kernel(const int* __restrict__ ei,
                                  const float* __restrict__ s, const float* __restrict__ d,
                                  float* __restrict__ emax)
{
    int e = blockIdx.x * blockDim.x + threadIdx.x;
    if (e >= E_TOT) return;
    int src, dst;
    if (e < N_EDGES) { src = ei[e]; dst = ei[N_EDGES + e]; }
    else             { src = dst = e - N_EDGES; }
#pragma unroll
    for (int h = 0; h < H; h++) {
        float v = lrelu(s[src * H + h] + d[dst * H + h]);
        atomicMaxFloat(&emax[dst * H + h], v);
    }
}

// ---------------------------------------------------------------------------
// edge pass 2: ee = exp(lrelu(s[src]+d[dst]) - emax[dst]); segment-sum into den
// ---------------------------------------------------------------------------
template<int H>
__global__ void edge_pass2_kernel(const int* __restrict__ ei,
                                  const float* __restrict__ s, const float* __restrict__ d,
                                  const float* __restrict__ emax,
                                  float* __restrict__ den, float* __restrict__ ee)
{
    int e = blockIdx.x * blockDim.x + threadIdx.x;
    if (e >= E_TOT) return;
    int src, dst;
    if (e < N_EDGES) { src = ei[e]; dst = ei[N_EDGES + e]; }
    else             { src = dst = e - N_EDGES; }
#pragma unroll
    for (int h = 0; h < H; h++) {
        float v  = lrelu(s[src * H + h] + d[dst * H + h]);
        float ex = __expf(v - emax[dst * H + h]);
        ee[(size_t)e * H + h] = ex;
        atomicAdd(&den[dst * H + h], ex);
    }
}

// ---------------------------------------------------------------------------
// den -> 1/(den + 1e-16)
// ---------------------------------------------------------------------------
__global__ void rcp_kernel(float* __restrict__ den, int n)
{
    int i = blockIdx.x * blockDim.x + threadIdx.x;
    if (i < n) den[i] = __frcp_rn(den[i] + 1e-16f);
}

// ---------------------------------------------------------------------------
// edge pass 3: acc[dst] += (ee * rden[dst]) * xp[src]; one warp per edge
// ---------------------------------------------------------------------------
template<int H, int C>
__global__ void edge_pass3_kernel(const int* __restrict__ ei,
                                  const float* __restrict__ ee, const float* __restrict__ rden,
                                  const float* __restrict__ xp, float* __restrict__ acc)
{
    constexpr int TOT = H * C;
    int wid  = (blockIdx.x * blockDim.x + threadIdx.x) >> 5;
    int lane = threadIdx.x & 31;
    if (wid >= E_TOT) return;
    int src, dst;
    if (wid < N_EDGES) { src = ei[wid]; dst = ei[N_EDGES + wid]; }
    else               { src = dst = wid - N_EDGES; }

#pragma unroll
    for (int idx = 0; idx < TOT; idx += 128) {
        int off = idx + lane * 4;
        if (off < TOT) {
            int h = off / C;
            float alpha = ee[(size_t)wid * H + h] * rden[dst * H + h];
            float4 v = *(const float4*)(xp + (size_t)src * TOT + off);
            red_add_v4(acc + (size_t)dst * TOT + off,
                       v.x * alpha, v.y * alpha, v.z * alpha, v.w * alpha);
        }
    }
}

// ---------------------------------------------------------------------------
// finalize: out = relu(acc + b)   (TOT is a power of two -> mask)
// ---------------------------------------------------------------------------
__global__ void bias_relu_kernel(const float* __restrict__ acc, const float* __restrict__ b,
                                 float* __restrict__ out, long long n, int mask)
{
    long long i = (long long)blockIdx.x * blockDim.x + threadIdx.x;
    if (i < n) out[i] = fmaxf(acc[i] + b[(int)(i & mask)], 0.f);
}

// ---------------------------------------------------------------------------
// FC: out[n,k] = sum_c h[n,c]*Wfc[c,k] + bfc[k]; one warp per node, C=64, K=10
// ---------------------------------------------------------------------------
__global__ void fc_kernel(const float* __restrict__ h, const float* __restrict__ Wfc,
                          const float* __restrict__ bfc, float* __restrict__ out)
{
    int wid  = (blockIdx.x * blockDim.x + threadIdx.x) >> 5;
    int lane = threadIdx.x & 31;
    if (wid >= N_NODES) return;
    float h0 = h[(size_t)wid * 64 + lane];
    float h1 = h[(size_t)wid * 64 + 32 + lane];
#pragma unroll
    for (int k = 0; k < 10; k++) {
        float p = fmaf(h0, Wfc[lane * 10 + k], h1 * Wfc[(lane + 32) * 10 + k]);
#pragma unroll
        for (int o = 16; o; o >>= 1) p += __shfl_down_sync(0xffffffffu, p, o);
        if (lane == 0) out[(size_t)wid * 10 + k] = p + bfc[k];
    }
}

// ---------------------------------------------------------------------------
// host-side layer runner
// ---------------------------------------------------------------------------
template<int H, int C>
static void run_gat_layer(const float* in, int F,
                          const float* W, const float* asrc, const float* adst, const float* bias,
                          const int* ei,
                          float* xp, float* acc, float* s, float* d,
                          float* emax, float* den, float* ee,
                          float* outbuf)
{
    constexpr int TOT = H * C;
    // xp = in @ W
    dim3 grid((N_NODES + 127) / 128, (TOT + 127) / 128);
    sgemm_kernel<<<grid, 256>>>(in, W, xp, N_NODES, TOT, F);
    // per-node attention projections
    int nw = N_NODES * H;
    sd_kernel<<<(nw * 32 + 255) / 256, 256>>>(xp, asrc, adst, s, d, H, C);
    // fused init (emax/den/acc)
    init_layer_kernel<<<4096, 256>>>(emax, den, N_NODES * H, acc, (long long)N_NODES * TOT);
    // edge passes
    edge_pass1_kernel<H><<<(E_TOT + 255) / 256, 256>>>(ei, s, d, emax);
    edge_pass2_kernel<H><<<(E_TOT + 255) / 256, 256>>>(ei, s, d, emax, den, ee);
    rcp_kernel<<<(N_NODES * H + 255) / 256, 256>>>(den, N_NODES * H);
    edge_pass3_kernel<H, C><<<(E_TOT * 32 + 255) / 256, 256>>>(ei, ee, den, xp, acc);
    // finalize
    long long tot = (long long)N_NODES * TOT;
    bias_relu_kernel<<<(int)((tot + 255) / 256), 256>>>(acc, bias, outbuf, tot, TOT - 1);
}

// ---------------------------------------------------------------------------
extern "C" void kernel_launch(void* const* d_in, const int* in_sizes, int n_in,
                              void* d_out, int out_size)
{
    const float* x    = (const float*)d_in[0];
    const int*   ei   = (const int*)  d_in[1];
    const float* W1   = (const float*)d_in[2];
    const float* as1  = (const float*)d_in[3];
    const float* ad1  = (const float*)d_in[4];
    const float* b1   = (const float*)d_in[5];
    const float* W2   = (const float*)d_in[6];
    const float* as2  = (const float*)d_in[7];
    const float* ad2  = (const float*)d_in[8];
    const float* b2   = (const float*)d_in[9];
    const float* W3   = (const float*)d_in[10];
    const float* as3  = (const float*)d_in[11];
    const float* ad3  = (const float*)d_in[12];
    const float* b3   = (const float*)d_in[13];
    const float* Wfc  = (const float*)d_in[14];
    const float* bfc  = (const float*)d_in[15];
    float* out = (float*)d_out;

    float *hbuf, *xp, *acc, *s, *d, *emax, *den, *ee;
    cudaGetSymbolAddress((void**)&hbuf, g_h);
    cudaGetSymbolAddress((void**)&xp,   g_xp);
    cudaGetSymbolAddress((void**)&acc,  g_acc);
    cudaGetSymbolAddress((void**)&s,    g_s);
    cudaGetSymbolAddress((void**)&d,    g_d);
    cudaGetSymbolAddress((void**)&emax, g_emax);
    cudaGetSymbolAddress((void**)&den,  g_den);
    cudaGetSymbolAddress((void**)&ee,   g_ee);

    // layer 1: in = x [N,128], H=4, C=64
    run_gat_layer<4, 64>(x, 128, W1, as1, ad1, b1, ei, xp, acc, s, d, emax, den, ee, hbuf);
    // layer 2: in = hbuf [N,256], H=4, C=64
    run_gat_layer<4, 64>(hbuf, 256, W2, as2, ad2, b2, ei, xp, acc, s, d, emax, den, ee, hbuf);
    // layer 3: in = hbuf [N,256], H=1, C=64
    run_gat_layer<1, 64>(hbuf, 256, W3, as3, ad3, b3, ei, xp, acc, s, d, emax, den, ee, hbuf);
    // FC head
    fc_kernel<<<(N_NODES * 32 + 255) / 256, 256>>>(hbuf, Wfc, bfc, out);
}

// round 6
// speedup vs baseline: 1.4258x; 1.4258x over previous
#include <cuda_runtime.h>
#include <cstdint>
#include <cstddef>

#define N_NODES   50000
#define N_EDGES   800000
#define E_TOT     850000   // edges + self loops
#define NEG_SLOPE 0.2f

// ---------------------------------------------------------------------------
// Static device scratch (allocation-free)
// ---------------------------------------------------------------------------
static __device__ __align__(256) float g_h  [(size_t)N_NODES * 256];  // layer io
static __device__ __align__(256) float g_xp [(size_t)N_NODES * 256];  // x @ W
static __device__ __align__(256) float g_s  [N_NODES * 4];
static __device__ __align__(256) float g_d  [N_NODES * 4];
static __device__ __align__(256) int   g_deg   [N_NODES];
static __device__ __align__(256) int   g_rowptr[N_NODES + 1];
static __device__ __align__(256) int   g_cursor[N_NODES];
static __device__ __align__(256) int   g_csr   [E_TOT];

// ---------------------------------------------------------------------------
// SGEMM: C[M,N] = A[M,K] @ B[K,N], row-major, fp32.
// BM=BN=128, BK=16, 256 threads, TM=TN=8, double-buffered smem.
// ---------------------------------------------------------------------------
__global__ __launch_bounds__(256)
void sgemm_kernel(const float* __restrict__ A, const float* __restrict__ B,
                  float* __restrict__ C, int M, int N, int K)
{
    constexpr int BM = 128, BN = 128, BK = 16, TM = 8, TN = 8;
    __shared__ float As[2][BK][BM];
    __shared__ float Bs[2][BK][BN];

    const int tid = threadIdx.x;
    const int tx = tid % (BN / TN);
    const int ty = tid / (BN / TN);
    const int rowBase = blockIdx.x * BM;
    const int colBase = blockIdx.y * BN;

    const int aRow = tid / 4;                // 0..63
    const int aCol = (tid % 4) * 4;          // 0,4,8,12
    const int bRow = tid / 32;               // 0..7
    const int bCol = (tid % 32) * 4;         // 0..124

    float acc[TM][TN];
#pragma unroll
    for (int i = 0; i < TM; i++)
#pragma unroll
        for (int j = 0; j < TN; j++) acc[i][j] = 0.f;

    const bool bColOk = (colBase + bCol) < N;

    {
        float4 a0 = make_float4(0.f,0.f,0.f,0.f), a1 = a0, b0 = a0, b1 = a0;
        int gr0 = rowBase + aRow, gr1 = gr0 + 64;
        if (gr0 < M) a0 = *(const float4*)&A[(size_t)gr0 * K + aCol];
        if (gr1 < M) a1 = *(const float4*)&A[(size_t)gr1 * K + aCol];
        if (bColOk) {
            b0 = *(const float4*)&B[(size_t)(bRow    ) * N + colBase + bCol];
            b1 = *(const float4*)&B[(size_t)(bRow + 8) * N + colBase + bCol];
        }
        As[0][aCol+0][aRow] = a0.x; As[0][aCol+1][aRow] = a0.y;
        As[0][aCol+2][aRow] = a0.z; As[0][aCol+3][aRow] = a0.w;
        As[0][aCol+0][aRow+64] = a1.x; As[0][aCol+1][aRow+64] = a1.y;
        As[0][aCol+2][aRow+64] = a1.z; As[0][aCol+3][aRow+64] = a1.w;
        *(float4*)&Bs[0][bRow    ][bCol] = b0;
        *(float4*)&Bs[0][bRow + 8][bCol] = b1;
    }
    __syncthreads();

    int buf = 0;
    for (int k0 = 0; k0 < K; k0 += BK) {
        float4 a0, a1, b0, b1;
        const bool hasNext = (k0 + BK) < K;
        if (hasNext) {
            a0 = make_float4(0.f,0.f,0.f,0.f); a1 = a0; b0 = a0; b1 = a0;
            int kn = k0 + BK;
            int gr0 = rowBase + aRow, gr1 = gr0 + 64;
            if (gr0 < M) a0 = *(const float4*)&A[(size_t)gr0 * K + kn + aCol];
            if (gr1 < M) a1 = *(const float4*)&A[(size_t)gr1 * K + kn + aCol];
            if (bColOk) {
                b0 = *(const float4*)&B[(size_t)(kn + bRow    ) * N + colBase + bCol];
                b1 = *(const float4*)&B[(size_t)(kn + bRow + 8) * N + colBase + bCol];
            }
        }

#pragma unroll
        for (int k = 0; k < BK; k++) {
            float ra[TM], rb[TN];
#pragma unroll
            for (int i = 0; i < TM; i++) ra[i] = As[buf][k][ty * TM + i];
#pragma unroll
            for (int j = 0; j < TN; j++) rb[j] = Bs[buf][k][tx * TN + j];
#pragma unroll
            for (int i = 0; i < TM; i++)
#pragma unroll
                for (int j = 0; j < TN; j++)
                    acc[i][j] = fmaf(ra[i], rb[j], acc[i][j]);
        }

        if (hasNext) {
            int nb = buf ^ 1;
            As[nb][aCol+0][aRow] = a0.x; As[nb][aCol+1][aRow] = a0.y;
            As[nb][aCol+2][aRow] = a0.z; As[nb][aCol+3][aRow] = a0.w;
            As[nb][aCol+0][aRow+64] = a1.x; As[nb][aCol+1][aRow+64] = a1.y;
            As[nb][aCol+2][aRow+64] = a1.z; As[nb][aCol+3][aRow+64] = a1.w;
            *(float4*)&Bs[nb][bRow    ][bCol] = b0;
            *(float4*)&Bs[nb][bRow + 8][bCol] = b1;
            __syncthreads();
            buf = nb;
        }
    }

#pragma unroll
    for (int i = 0; i < TM; i++) {
        int gr = rowBase + ty * TM + i;
        if (gr >= M) continue;
        int gc = colBase + tx * TN;
        if (gc >= N) continue;
#pragma unroll
        for (int j = 0; j < TN; j += 4) {
            float4 v = make_float4(acc[i][j], acc[i][j+1], acc[i][j+2], acc[i][j+3]);
            *(float4*)&C[(size_t)gr * N + gc + j] = v;
        }
    }
}

// ---------------------------------------------------------------------------
// s[n,h] = <xp[n,h,:], a_src[h,:]>, d[n,h] = <xp[n,h,:], a_dst[h,:]>
// ---------------------------------------------------------------------------
__global__ void sd_kernel(const float* __restrict__ xp,
                          const float* __restrict__ asrc, const float* __restrict__ adst,
                          float* __restrict__ s, float* __restrict__ d,
                          int H, int C)
{
    int wid  = (blockIdx.x * blockDim.x + threadIdx.x) >> 5;
    int lane = threadIdx.x & 31;
    if (wid >= N_NODES * H) return;
    int n = wid / H, h = wid % H;
    const float* row = xp + (size_t)n * H * C + (size_t)h * C;
    float vs = 0.f, vd = 0.f;
    for (int c = lane; c < C; c += 32) {
        float v = row[c];
        vs = fmaf(v, asrc[h * C + c], vs);
        vd = fmaf(v, adst[h * C + c], vd);
    }
#pragma unroll
    for (int o = 16; o; o >>= 1) {
        vs += __shfl_down_sync(0xffffffffu, vs, o);
        vd += __shfl_down_sync(0xffffffffu, vd, o);
    }
    if (lane == 0) { s[wid] = vs; d[wid] = vd; }
}

// ---------------------------------------------------------------------------
// CSR build (once per launch, reused by all 3 layers)
// ---------------------------------------------------------------------------
__global__ void deg_init_kernel(int* __restrict__ deg)
{
    int i = blockIdx.x * blockDim.x + threadIdx.x;
    if (i < N_NODES) deg[i] = 1;   // self loop
}

__global__ void deg_hist_kernel(const int* __restrict__ ei, int* __restrict__ deg)
{
    int e = blockIdx.x * blockDim.x + threadIdx.x;
    if (e < N_EDGES) atomicAdd(&deg[ei[N_EDGES + e]], 1);
}

// single-block exclusive scan over N_NODES ints; rowptr[N_NODES] = total
__global__ __launch_bounds__(1024) void scan_kernel(const int* __restrict__ deg,
                                                    int* __restrict__ rowptr)
{
    __shared__ int wsum[32];
    __shared__ int carry_s;
    const int t = threadIdx.x;
    const int lane = t & 31, wid = t >> 5;
    if (t == 0) carry_s = 0;
    __syncthreads();
    for (int base = 0; base < N_NODES; base += 1024) {
        int i = base + t;
        int v = (i < N_NODES) ? deg[i] : 0;
        int x = v;
#pragma unroll
        for (int o = 1; o < 32; o <<= 1) {
            int y = __shfl_up_sync(0xffffffffu, x, o);
            if (lane >= o) x += y;
        }
        if (lane == 31) wsum[wid] = x;
        int carry = carry_s;
        __syncthreads();
        if (t < 32) {
            int y = wsum[t];
#pragma unroll
            for (int o = 1; o < 32; o <<= 1) {
                int z = __shfl_up_sync(0xffffffffu, y, o);
                if (t >= o) y += z;
            }
            wsum[t] = y;   // inclusive over warp totals
        }
        __syncthreads();
        int woff = wid ? wsum[wid - 1] : 0;
        if (i < N_NODES) rowptr[i] = carry + woff + x - v;
        int total = wsum[31];
        __syncthreads();
        if (t == 0) carry_s = carry + total;
        __syncthreads();
    }
    if (t == 0) rowptr[N_NODES] = carry_s;
}

__global__ void self_loop_kernel(const int* __restrict__ rowptr,
                                 int* __restrict__ csr, int* __restrict__ cursor)
{
    int n = blockIdx.x * blockDim.x + threadIdx.x;
    if (n < N_NODES) {
        int p = rowptr[n];
        csr[p] = n;           // self loop first (deterministic slot)
        cursor[n] = p + 1;
    }
}

__global__ void scatter_kernel(const int* __restrict__ ei,
                               int* __restrict__ cursor, int* __restrict__ csr)
{
    int e = blockIdx.x * blockDim.x + threadIdx.x;
    if (e < N_EDGES) {
        int dst = ei[N_EDGES + e];
        int p = atomicAdd(&cursor[dst], 1);
        csr[p] = ei[e];
    }
}

// ---------------------------------------------------------------------------
// Fused GAT attention + aggregation: one block per dst node.
// sweep1: segment max; sweep2: segment denom; sweep3: chunked alpha staging
// + coalesced gather-accumulate of xp[src]; epilogue relu(+bias).
// THREADS * VEC == H * 64.
// ---------------------------------------------------------------------------
template<int H, int THREADS, int VEC>
__global__ __launch_bounds__(THREADS)
void gat_aggregate_kernel(const int* __restrict__ rowptr, const int* __restrict__ csr,
                          const float* __restrict__ s, const float* __restrict__ dvec,
                          const float* __restrict__ xp, const float* __restrict__ bias,
                          float* __restrict__ out)
{
    constexpr int TOT = H * 64;
    constexpr int CHUNK = THREADS;
    const int dst = blockIdx.x;
    const int t = threadIdx.x;
    const int rs = rowptr[dst], re = rowptr[dst + 1];

    __shared__ float sm_d[H];
    __shared__ float sm_m[H];
    __shared__ float sm_r[H];
    __shared__ float red[THREADS];
    __shared__ int   s_src[CHUNK];
    __shared__ float s_alpha[CHUNK * H];

    if (t < H) sm_d[t] = dvec[dst * H + t];
    __syncthreads();

    const int h = t % H;
    const float dh = sm_d[h];

    // sweep 1: per-head max over in-edges
    float lm = -3.402823466e38f;
    for (int i = rs + t / H; i < re; i += THREADS / H) {
        int src = csr[i];
        float v = s[src * H + h] + dh;
        v = v > 0.f ? v : NEG_SLOPE * v;
        lm = fmaxf(lm, v);
    }
    red[t] = lm;
    __syncthreads();
#pragma unroll
    for (int off = THREADS / 2; off >= H; off >>= 1) {
        if (t < off) red[t] = fmaxf(red[t], red[t + off]);
        __syncthreads();
    }
    if (t < H) sm_m[t] = red[t];
    __syncthreads();
    const float mh = sm_m[h];

    // sweep 2: per-head denom
    float ls = 0.f;
    for (int i = rs + t / H; i < re; i += THREADS / H) {
        int src = csr[i];
        float v = s[src * H + h] + dh;
        v = v > 0.f ? v : NEG_SLOPE * v;
        ls += __expf(v - mh);
    }
    __syncthreads();
    red[t] = ls;
    __syncthreads();
#pragma unroll
    for (int off = THREADS / 2; off >= H; off >>= 1) {
        if (t < off) red[t] += red[t + off];
        __syncthreads();
    }
    if (t < H) sm_r[t] = __frcp_rn(red[t] + 1e-16f);
    __syncthreads();

    // sweep 3: gather-accumulate
    const int myh = (t * VEC) / 64;
    float acc[VEC];
#pragma unroll
    for (int j = 0; j < VEC; j++) acc[j] = 0.f;

    for (int pos = rs; pos < re; pos += CHUNK) {
        const int count = min(CHUNK, re - pos);
        if (t < count) {
            int src = csr[pos + t];
            s_src[t] = src;
#pragma unroll
            for (int hh = 0; hh < H; hh++) {
                float v = s[src * H + hh] + sm_d[hh];
                v = v > 0.f ? v : NEG_SLOPE * v;
                s_alpha[t * H + hh] = __expf(v - sm_m[hh]) * sm_r[hh];
            }
        }
        __syncthreads();
        int e = 0;
        for (; e + 2 <= count; e += 2) {
            float a0 = s_alpha[(e    ) * H + myh];
            float a1 = s_alpha[(e + 1) * H + myh];
            const float* r0 = xp + (size_t)s_src[e    ] * TOT + t * VEC;
            const float* r1 = xp + (size_t)s_src[e + 1] * TOT + t * VEC;
            if (VEC == 4) {
                float4 v0 = *(const float4*)r0;
                float4 v1 = *(const float4*)r1;
                acc[0] = fmaf(a0, v0.x, acc[0]); acc[1] = fmaf(a0, v0.y, acc[1]);
                acc[2] = fmaf(a0, v0.z, acc[2]); acc[3] = fmaf(a0, v0.w, acc[3]);
                acc[0] = fmaf(a1, v1.x, acc[0]); acc[1] = fmaf(a1, v1.y, acc[1]);
                acc[2] = fmaf(a1, v1.z, acc[2]); acc[3] = fmaf(a1, v1.w, acc[3]);
            } else {
                float2 v0 = *(const float2*)r0;
                float2 v1 = *(const float2*)r1;
                acc[0] = fmaf(a0, v0.x, acc[0]); acc[1] = fmaf(a0, v0.y, acc[1]);
                acc[0] = fmaf(a1, v1.x, acc[0]); acc[1] = fmaf(a1, v1.y, acc[1]);
            }
        }
        if (e < count) {
            float a0 = s_alpha[e * H + myh];
            const float* r0 = xp + (size_t)s_src[e] * TOT + t * VEC;
            if (VEC == 4) {
                float4 v0 = *(const float4*)r0;
                acc[0] = fmaf(a0, v0.x, acc[0]); acc[1] = fmaf(a0, v0.y, acc[1]);
                acc[2] = fmaf(a0, v0.z, acc[2]); acc[3] = fmaf(a0, v0.w, acc[3]);
            } else {
                float2 v0 = *(const float2*)r0;
                acc[0] = fmaf(a0, v0.x, acc[0]); acc[1] = fmaf(a0, v0.y, acc[1]);
            }
        }
        __syncthreads();
    }

#pragma unroll
    for (int j = 0; j < VEC; j++) {
        int c = t * VEC + j;
        out[(size_t)dst * TOT + c] = fmaxf(acc[j] + bias[c], 0.f);
    }
}

// ---------------------------------------------------------------------------
// FC: out[n,k] = sum_c h[n,c]*Wfc[c,k] + bfc[k]; one warp per node
// ---------------------------------------------------------------------------
__global__ void fc_kernel(const float* __restrict__ h, const float* __restrict__ Wfc,
                          const float* __restrict__ bfc, float* __restrict__ out)
{
    int wid  = (blockIdx.x * blockDim.x + threadIdx.x) >> 5;
    int lane = threadIdx.x & 31;
    if (wid >= N_NODES) return;
    float h0 = h[(size_t)wid * 64 + lane];
    float h1 = h[(size_t)wid * 64 + 32 + lane];
#pragma unroll
    for (int k = 0; k < 10; k++) {
        float p = fmaf(h0, Wfc[lane * 10 + k], h1 * Wfc[(lane + 32) * 10 + k]);
#pragma unroll
        for (int o = 16; o; o >>= 1) p += __shfl_down_sync(0xffffffffu, p, o);
        if (lane == 0) out[(size_t)wid * 10 + k] = p + bfc[k];
    }
}

// ---------------------------------------------------------------------------
// host-side layer runner
// ---------------------------------------------------------------------------
template<int H, int THREADS, int VEC>
static void run_gat_layer(const float* in, int F,
                          const float* W, const float* asrc, const float* adst,
                          const float* bias,
                          const int* rowptr, const int* csr,
                          float* xp, float* s, float* d, float* outbuf)
{
    constexpr int TOT = H * 64;
    dim3 grid((N_NODES + 127) / 128, (TOT + 127) / 128);
    sgemm_kernel<<<grid, 256>>>(in, W, xp, N_NODES, TOT, F);
    int nw = N_NODES * H;
    sd_kernel<<<(nw * 32 + 255) / 256, 256>>>(xp, asrc, adst, s, d, H, 64);
    gat_aggregate_kernel<H, THREADS, VEC><<<N_NODES, THREADS>>>(
        rowptr, csr, s, d, xp, bias, outbuf);
}

// ---------------------------------------------------------------------------
extern "C" void kernel_launch(void* const* d_in, const int* in_sizes, int n_in,
                              void* d_out, int out_size)
{
    const float* x    = (const float*)d_in[0];
    const int*   ei   = (const int*)  d_in[1];
    const float* W1   = (const float*)d_in[2];
    const float* as1  = (const float*)d_in[3];
    const float* ad1  = (const float*)d_in[4];
    const float* b1   = (const float*)d_in[5];
    const float* W2   = (const float*)d_in[6];
    const float* as2  = (const float*)d_in[7];
    const float* ad2  = (const float*)d_in[8];
    const float* b2   = (const float*)d_in[9];
    const float* W3   = (const float*)d_in[10];
    const float* as3  = (const float*)d_in[11];
    const float* ad3  = (const float*)d_in[12];
    const float* b3   = (const float*)d_in[13];
    const float* Wfc  = (const float*)d_in[14];
    const float* bfc  = (const float*)d_in[15];
    float* out = (float*)d_out;

    float *hbuf, *xp, *s, *d;
    int *deg, *rowptr, *cursor, *csr;
    cudaGetSymbolAddress((void**)&hbuf,   g_h);
    cudaGetSymbolAddress((void**)&xp,     g_xp);
    cudaGetSymbolAddress((void**)&s,      g_s);
    cudaGetSymbolAddress((void**)&d,      g_d);
    cudaGetSymbolAddress((void**)&deg,    g_deg);
    cudaGetSymbolAddress((void**)&rowptr, g_rowptr);
    cudaGetSymbolAddress((void**)&cursor, g_cursor);
    cudaGetSymbolAddress((void**)&csr,    g_csr);

    // ---- CSR build (dst-sorted adjacency, self loop first in each segment) ----
    deg_init_kernel<<<(N_NODES + 255) / 256, 256>>>(deg);
    deg_hist_kernel<<<(N_EDGES + 255) / 256, 256>>>(ei, deg);
    scan_kernel<<<1, 1024>>>(deg, rowptr);
    self_loop_kernel<<<(N_NODES + 255) / 256, 256>>>(rowptr, csr, cursor);
    scatter_kernel<<<(N_EDGES + 255) / 256, 256>>>(ei, cursor, csr);

    // ---- layers ----
    run_gat_layer<4, 64, 4>(x,    128, W1, as1, ad1, b1, rowptr, csr, xp, s, d, hbuf);
    run_gat_layer<4, 64, 4>(hbuf, 256, W2, as2, ad2, b2, rowptr, csr, xp, s, d, hbuf);
    run_gat_layer<1, 32, 2>(hbuf, 256, W3, as3, ad3, b3, rowptr, csr, xp, s, d, hbuf);

    // ---- FC head ----
    fc_kernel<<<(N_NODES * 32 + 255) / 256, 256>>>(hbuf, Wfc, bfc, out);
}

// round 7
// speedup vs baseline: 1.7200x; 1.2063x over previous
#include <cuda_runtime.h>
#include <cstdint>
#include <cstddef>

#define N_NODES   50000
#define N_EDGES   800000
#define E_TOT     850000   // edges + self loops
#define NEG_SLOPE 0.2f

// ---------------------------------------------------------------------------
// Static device scratch (allocation-free)
// ---------------------------------------------------------------------------
static __device__ __align__(256) float g_h  [(size_t)N_NODES * 256];  // layer io
static __device__ __align__(256) float g_xp [(size_t)N_NODES * 256];  // x @ W
static __device__ __align__(256) float g_s  [N_NODES * 4];
static __device__ __align__(256) float g_d  [N_NODES * 4];
static __device__ __align__(256) int   g_deg   [N_NODES];
static __device__ __align__(256) int   g_rowptr[N_NODES + 1];
static __device__ __align__(256) int   g_cursor[N_NODES];
static __device__ __align__(256) int   g_csr   [E_TOT];

// ---------------------------------------------------------------------------
// tf32 helpers (3xTF32 decomposition: x ~= hi + lo, both tf32)
// ---------------------------------------------------------------------------
__device__ __forceinline__ uint32_t f2tf32(float x) {
    uint32_t r;
    asm("cvt.rna.tf32.f32 %0, %1;" : "=r"(r) : "f"(x));
    return r;
}

__device__ __forceinline__ void decomp(float x, uint32_t& hi, uint32_t& lo) {
    hi = f2tf32(x);
    lo = f2tf32(x - __uint_as_float(hi));
}

__device__ __forceinline__ void mma_tf32(float* c,
                                         uint32_t a0, uint32_t a1, uint32_t a2, uint32_t a3,
                                         uint32_t b0, uint32_t b1) {
    asm volatile("mma.sync.aligned.m16n8k8.row.col.f32.tf32.tf32.f32 "
                 "{%0,%1,%2,%3}, {%4,%5,%6,%7}, {%8,%9}, {%0,%1,%2,%3};"
                 : "+f"(c[0]), "+f"(c[1]), "+f"(c[2]), "+f"(c[3])
                 : "r"(a0), "r"(a1), "r"(a2), "r"(a3), "r"(b0), "r"(b1));
}

// ---------------------------------------------------------------------------
// 3xTF32 tensor-core GEMM: C[M,N] = A[M,K] @ B[K,N], row-major fp32 in/out.
// BM=BN=128, BK=16, 256 threads (8 warps, 64x32 warp tiles).
// K must be a multiple of 16. Row guard on A/C, col guard on B/C.
// ---------------------------------------------------------------------------
__global__ __launch_bounds__(256)
void tf32_gemm_kernel(const float* __restrict__ A, const float* __restrict__ B,
                      float* __restrict__ C, int M, int N, int K)
{
    constexpr int BM = 128, BN = 128, BK = 16;
    constexpr int AST = BK + 4;    // A smem stride (floats) — conflict-free frag loads
    constexpr int BST = BN + 8;    // B smem stride

    __shared__ uint32_t As[2][BM * AST];   // [hi/lo][m*AST + k]
    __shared__ uint32_t Bs[2][BK * BST];   // [hi/lo][k*BST + n]

    const int tid  = threadIdx.x;
    const int lane = tid & 31;
    const int wid  = tid >> 5;
    const int gid  = lane >> 2;     // 0..7
    const int tg   = lane & 3;      // 0..3
    const int wm   = (wid & 1) * 64;
    const int wn   = (wid >> 1) * 32;
    const int rowBase = blockIdx.x * BM;
    const int colBase = blockIdx.y * BN;

    // global-load assignments
    const int aR = tid >> 2;          // 0..63  (rows aR, aR+64)
    const int aC = (tid & 3) * 4;     // 0,4,8,12
    const int bR = tid >> 5;          // 0..7   (rows bR, bR+8)
    const int bC = (tid & 31) * 4;    // 0..124

    const bool bColOk = (colBase + bC) < N;

    float c[4][4][4];
#pragma unroll
    for (int mi = 0; mi < 4; mi++)
#pragma unroll
        for (int ni = 0; ni < 4; ni++)
#pragma unroll
            for (int f = 0; f < 4; f++) c[mi][ni][f] = 0.f;

    float4 pa0, pa1, pb0, pb1;

    // prologue: load tile 0
    {
        const float4 z = make_float4(0.f, 0.f, 0.f, 0.f);
        pa0 = z; pa1 = z; pb0 = z; pb1 = z;
        int r0 = rowBase + aR, r1 = r0 + 64;
        if (r0 < M) pa0 = *(const float4*)&A[(size_t)r0 * K + aC];
        if (r1 < M) pa1 = *(const float4*)&A[(size_t)r1 * K + aC];
        if (bColOk) {
            pb0 = *(const float4*)&B[(size_t)(bR    ) * N + colBase + bC];
            pb1 = *(const float4*)&B[(size_t)(bR + 8) * N + colBase + bC];
        }
    }

    for (int k0 = 0; k0 < K; k0 += BK) {
        // ---- decompose + store current tile to smem ----
        {
            uint32_t h[4], l[4];
            decomp(pa0.x, h[0], l[0]); decomp(pa0.y, h[1], l[1]);
            decomp(pa0.z, h[2], l[2]); decomp(pa0.w, h[3], l[3]);
            *(uint4*)&As[0][aR * AST + aC] = make_uint4(h[0], h[1], h[2], h[3]);
            *(uint4*)&As[1][aR * AST + aC] = make_uint4(l[0], l[1], l[2], l[3]);
            decomp(pa1.x, h[0], l[0]); decomp(pa1.y, h[1], l[1]);
            decomp(pa1.z, h[2], l[2]); decomp(pa1.w, h[3], l[3]);
            *(uint4*)&As[0][(aR + 64) * AST + aC] = make_uint4(h[0], h[1], h[2], h[3]);
            *(uint4*)&As[1][(aR + 64) * AST + aC] = make_uint4(l[0], l[1], l[2], l[3]);
            decomp(pb0.x, h[0], l[0]); decomp(pb0.y, h[1], l[1]);
            decomp(pb0.z, h[2], l[2]); decomp(pb0.w, h[3], l[3]);
            *(uint4*)&Bs[0][bR * BST + bC] = make_uint4(h[0], h[1], h[2], h[3]);
            *(uint4*)&Bs[1][bR * BST + bC] = make_uint4(l[0], l[1], l[2], l[3]);
            decomp(pb1.x, h[0], l[0]); decomp(pb1.y, h[1], l[1]);
            decomp(pb1.z, h[2], l[2]); decomp(pb1.w, h[3], l[3]);
            *(uint4*)&Bs[0][(bR + 8) * BST + bC] = make_uint4(h[0], h[1], h[2], h[3]);
            *(uint4*)&Bs[1][(bR + 8) * BST + bC] = make_uint4(l[0], l[1], l[2], l[3]);
        }
        __syncthreads();

        // ---- prefetch next tile (overlaps with MMA compute) ----
        if (k0 + BK < K) {
            const float4 z = make_float4(0.f, 0.f, 0.f, 0.f);
            pa0 = z; pa1 = z; pb0 = z; pb1 = z;
            int kn = k0 + BK;
            int r0 = rowBase + aR, r1 = r0 + 64;
            if (r0 < M) pa0 = *(const float4*)&A[(size_t)r0 * K + kn + aC];
            if (r1 < M) pa1 = *(const float4*)&A[(size_t)r1 * K + kn + aC];
            if (bColOk) {
                pb0 = *(const float4*)&B[(size_t)(kn + bR    ) * N + colBase + bC];
                pb1 = *(const float4*)&B[(size_t)(kn + bR + 8) * N + colBase + bC];
            }
        }

        // ---- compute: two k8 steps ----
#pragma unroll
        for (int ks = 0; ks < 2; ks++) {
            const int kb = ks * 8;
            uint32_t bh[4][2], bl[4][2];
#pragma unroll
            for (int ni = 0; ni < 4; ni++) {
                int n = wn + ni * 8 + gid;
                bh[ni][0] = Bs[0][(kb + tg    ) * BST + n];
                bh[ni][1] = Bs[0][(kb + tg + 4) * BST + n];
                bl[ni][0] = Bs[1][(kb + tg    ) * BST + n];
                bl[ni][1] = Bs[1][(kb + tg + 4) * BST + n];
            }
#pragma unroll
            for (int mi = 0; mi < 4; mi++) {
                int m = wm + mi * 16;
                uint32_t ah[4], al[4];
                ah[0] = As[0][(m + gid    ) * AST + kb + tg    ];
                ah[1] = As[0][(m + gid + 8) * AST + kb + tg    ];
                ah[2] = As[0][(m + gid    ) * AST + kb + tg + 4];
                ah[3] = As[0][(m + gid + 8) * AST + kb + tg + 4];
                al[0] = As[1][(m + gid    ) * AST + kb + tg    ];
                al[1] = As[1][(m + gid + 8) * AST + kb + tg    ];
                al[2] = As[1][(m + gid    ) * AST + kb + tg + 4];
                al[3] = As[1][(m + gid + 8) * AST + kb + tg + 4];
#pragma unroll
                for (int ni = 0; ni < 4; ni++) {
                    mma_tf32(c[mi][ni], al[0], al[1], al[2], al[3], bh[ni][0], bh[ni][1]);
                    mma_tf32(c[mi][ni], ah[0], ah[1], ah[2], ah[3], bl[ni][0], bl[ni][1]);
                    mma_tf32(c[mi][ni], ah[0], ah[1], ah[2], ah[3], bh[ni][0], bh[ni][1]);
                }
            }
        }
        __syncthreads();
    }

    // ---- epilogue ----
#pragma unroll
    for (int mi = 0; mi < 4; mi++) {
#pragma unroll
        for (int ni = 0; ni < 4; ni++) {
            int gr0 = rowBase + wm + mi * 16 + gid;
            int gr1 = gr0 + 8;
            int gc  = colBase + wn + ni * 8 + tg * 2;
            if (gc < N) {   // N multiple of 8 -> gc+1 < N
                if (gr0 < M)
                    *(float2*)&C[(size_t)gr0 * N + gc] = make_float2(c[mi][ni][0], c[mi][ni][1]);
                if (gr1 < M)
                    *(float2*)&C[(size_t)gr1 * N + gc] = make_float2(c[mi][ni][2], c[mi][ni][3]);
            }
        }
    }
}

// ---------------------------------------------------------------------------
// s[n,h] = <xp[n,h,:], a_src[h,:]>, d[n,h] = <xp[n,h,:], a_dst[h,:]>
// ---------------------------------------------------------------------------
__global__ void sd_kernel(const float* __restrict__ xp,
                          const float* __restrict__ asrc, const float* __restrict__ adst,
                          float* __restrict__ s, float* __restrict__ d,
                          int H, int C)
{
    int wid  = (blockIdx.x * blockDim.x + threadIdx.x) >> 5;
    int lane = threadIdx.x & 31;
    if (wid >= N_NODES * H) return;
    int n = wid / H, h = wid % H;
    const float* row = xp + (size_t)n * H * C + (size_t)h * C;
    float vs = 0.f, vd = 0.f;
    for (int c = lane; c < C; c += 32) {
        float v = row[c];
        vs = fmaf(v, asrc[h * C + c], vs);
        vd = fmaf(v, adst[h * C + c], vd);
    }
#pragma unroll
    for (int o = 16; o; o >>= 1) {
        vs += __shfl_down_sync(0xffffffffu, vs, o);
        vd += __shfl_down_sync(0xffffffffu, vd, o);
    }
    if (lane == 0) { s[wid] = vs; d[wid] = vd; }
}

// ---------------------------------------------------------------------------
// CSR build (once per launch, reused by all 3 layers)
// ---------------------------------------------------------------------------
__global__ void deg_init_kernel(int* __restrict__ deg)
{
    int i = blockIdx.x * blockDim.x + threadIdx.x;
    if (i < N_NODES) deg[i] = 1;   // self loop
}

__global__ void deg_hist_kernel(const int* __restrict__ ei, int* __restrict__ deg)
{
    int e = blockIdx.x * blockDim.x + threadIdx.x;
    if (e < N_EDGES) atomicAdd(&deg[ei[N_EDGES + e]], 1);
}

// single-block exclusive scan over N_NODES ints; rowptr[N_NODES] = total
__global__ __launch_bounds__(1024) void scan_kernel(const int* __restrict__ deg,
                                                    int* __restrict__ rowptr)
{
    __shared__ int wsum[32];
    __shared__ int carry_s;
    const int t = threadIdx.x;
    const int lane = t & 31, wid = t >> 5;
    if (t == 0) carry_s = 0;
    __syncthreads();
    for (int base = 0; base < N_NODES; base += 1024) {
        int i = base + t;
        int v = (i < N_NODES) ? deg[i] : 0;
        int x = v;
#pragma unroll
        for (int o = 1; o < 32; o <<= 1) {
            int y = __shfl_up_sync(0xffffffffu, x, o);
            if (lane >= o) x += y;
        }
        if (lane == 31) wsum[wid] = x;
        int carry = carry_s;
        __syncthreads();
        if (t < 32) {
            int y = wsum[t];
#pragma unroll
            for (int o = 1; o < 32; o <<= 1) {
                int z = __shfl_up_sync(0xffffffffu, y, o);
                if (t >= o) y += z;
            }
            wsum[t] = y;   // inclusive over warp totals
        }
        __syncthreads();
        int woff = wid ? wsum[wid - 1] : 0;
        if (i < N_NODES) rowptr[i] = carry + woff + x - v;
        int total = wsum[31];
        __syncthreads();
        if (t == 0) carry_s = carry + total;
        __syncthreads();
    }
    if (t == 0) rowptr[N_NODES] = carry_s;
}

__global__ void self_loop_kernel(const int* __restrict__ rowptr,
                                 int* __restrict__ csr, int* __restrict__ cursor)
{
    int n = blockIdx.x * blockDim.x + threadIdx.x;
    if (n < N_NODES) {
        int p = rowptr[n];
        csr[p] = n;           // self loop first (deterministic slot)
        cursor[n] = p + 1;
    }
}

__global__ void scatter_kernel(const int* __restrict__ ei,
                               int* __restrict__ cursor, int* __restrict__ csr)
{
    int e = blockIdx.x * blockDim.x + threadIdx.x;
    if (e < N_EDGES) {
        int dst = ei[N_EDGES + e];
        int p = atomicAdd(&cursor[dst], 1);
        csr[p] = ei[e];
    }
}

// ---------------------------------------------------------------------------
// Fused GAT attention + aggregation: one block per dst node.
// THREADS * VEC == H * 64.
// ---------------------------------------------------------------------------
template<int H, int THREADS, int VEC>
__global__ __launch_bounds__(THREADS)
void gat_aggregate_kernel(const int* __restrict__ rowptr, const int* __restrict__ csr,
                          const float* __restrict__ s, const float* __restrict__ dvec,
                          const float* __restrict__ xp, const float* __restrict__ bias,
                          float* __restrict__ out)
{
    constexpr int TOT = H * 64;
    constexpr int CHUNK = THREADS;
    const int dst = blockIdx.x;
    const int t = threadIdx.x;
    const int rs = rowptr[dst], re = rowptr[dst + 1];

    __shared__ float sm_d[H];
    __shared__ float sm_m[H];
    __shared__ float sm_r[H];
    __shared__ float red[THREADS];
    __shared__ int   s_src[CHUNK];
    __shared__ float s_alpha[CHUNK * H];

    if (t < H) sm_d[t] = dvec[dst * H + t];
    __syncthreads();

    const int h = t % H;
    const float dh = sm_d[h];

    // sweep 1: per-head max over in-edges
    float lm = -3.402823466e38f;
    for (int i = rs + t / H; i < re; i += THREADS / H) {
        int src = csr[i];
        float v = s[src * H + h] + dh;
        v = v > 0.f ? v : NEG_SLOPE * v;
        lm = fmaxf(lm, v);
    }
    red[t] = lm;
    __syncthreads();
#pragma unroll
    for (int off = THREADS / 2; off >= H; off >>= 1) {
        if (t < off) red[t] = fmaxf(red[t], red[t + off]);
        __syncthreads();
    }
    if (t < H) sm_m[t] = red[t];
    __syncthreads();
    const float mh = sm_m[h];

    // sweep 2: per-head denom
    float ls = 0.f;
    for (int i = rs + t / H; i < re; i += THREADS / H) {
        int src = csr[i];
        float v = s[src * H + h] + dh;
        v = v > 0.f ? v : NEG_SLOPE * v;
        ls += __expf(v - mh);
    }
    __syncthreads();
    red[t] = ls;
    __syncthreads();
#pragma unroll
    for (int off = THREADS / 2; off >= H; off >>= 1) {
        if (t < off) red[t] += red[t + off];
        __syncthreads();
    }
    if (t < H) sm_r[t] = __frcp_rn(red[t] + 1e-16f);
    __syncthreads();

    // sweep 3: gather-accumulate
    const int myh = (t * VEC) / 64;
    float acc[VEC];
#pragma unroll
    for (int j = 0; j < VEC; j++) acc[j] = 0.f;

    for (int pos = rs; pos < re; pos += CHUNK) {
        const int count = min(CHUNK, re - pos);
        if (t < count) {
            int src = csr[pos + t];
            s_src[t] = src;
#pragma unroll
            for (int hh = 0; hh < H; hh++) {
                float v = s[src * H + hh] + sm_d[hh];
                v = v > 0.f ? v : NEG_SLOPE * v;
                s_alpha[t * H + hh] = __expf(v - sm_m[hh]) * sm_r[hh];
            }
        }
        __syncthreads();
        int e = 0;
        for (; e + 2 <= count; e += 2) {
            float a0 = s_alpha[(e    ) * H + myh];
            float a1 = s_alpha[(e + 1) * H + myh];
            const float* r0 = xp + (size_t)s_src[e    ] * TOT + t * VEC;
            const float* r1 = xp + (size_t)s_src[e + 1] * TOT + t * VEC;
            if (VEC == 4) {
                float4 v0 = *(const float4*)r0;
                float4 v1 = *(const float4*)r1;
                acc[0] = fmaf(a0, v0.x, acc[0]); acc[1] = fmaf(a0, v0.y, acc[1]);
                acc[2] = fmaf(a0, v0.z, acc[2]); acc[3] = fmaf(a0, v0.w, acc[3]);
                acc[0] = fmaf(a1, v1.x, acc[0]); acc[1] = fmaf(a1, v1.y, acc[1]);
                acc[2] = fmaf(a1, v1.z, acc[2]); acc[3] = fmaf(a1, v1.w, acc[3]);
            } else {
                float2 v0 = *(const float2*)r0;
                float2 v1 = *(const float2*)r1;
                acc[0] = fmaf(a0, v0.x, acc[0]); acc[1] = fmaf(a0, v0.y, acc[1]);
                acc[0] = fmaf(a1, v1.x, acc[0]); acc[1] = fmaf(a1, v1.y, acc[1]);
            }
        }
        if (e < count) {
            float a0 = s_alpha[e * H + myh];
            const float* r0 = xp + (size_t)s_src[e] * TOT + t * VEC;
            if (VEC == 4) {
                float4 v0 = *(const float4*)r0;
                acc[0] = fmaf(a0, v0.x, acc[0]); acc[1] = fmaf(a0, v0.y, acc[1]);
                acc[2] = fmaf(a0, v0.z, acc[2]); acc[3] = fmaf(a0, v0.w, acc[3]);
            } else {
                float2 v0 = *(const float2*)r0;
                acc[0] = fmaf(a0, v0.x, acc[0]); acc[1] = fmaf(a0, v0.y, acc[1]);
            }
        }
        __syncthreads();
    }

#pragma unroll
    for (int j = 0; j < VEC; j++) {
        int c = t * VEC + j;
        out[(size_t)dst * TOT + c] = fmaxf(acc[j] + bias[c], 0.f);
    }
}

// ---------------------------------------------------------------------------
// FC: out[n,k] = sum_c h[n,c]*Wfc[c,k] + bfc[k]; one warp per node
// ---------------------------------------------------------------------------
__global__ void fc_kernel(const float* __restrict__ h, const float* __restrict__ Wfc,
                          const float* __restrict__ bfc, float* __restrict__ out)
{
    int wid  = (blockIdx.x * blockDim.x + threadIdx.x) >> 5;
    int lane = threadIdx.x & 31;
    if (wid >= N_NODES) return;
    float h0 = h[(size_t)wid * 64 + lane];
    float h1 = h[(size_t)wid * 64 + 32 + lane];
#pragma unroll
    for (int k = 0; k < 10; k++) {
        float p = fmaf(h0, Wfc[lane * 10 + k], h1 * Wfc[(lane + 32) * 10 + k]);
#pragma unroll
        for (int o = 16; o; o >>= 1) p += __shfl_down_sync(0xffffffffu, p, o);
        if (lane == 0) out[(size_t)wid * 10 + k] = p + bfc[k];
    }
}

// ---------------------------------------------------------------------------
// host-side layer runner
// ---------------------------------------------------------------------------
template<int H, int THREADS, int VEC>
static void run_gat_layer(const float* in, int F,
                          const float* W, const float* asrc, const float* adst,
                          const float* bias,
                          const int* rowptr, const int* csr,
                          float* xp, float* s, float* d, float* outbuf)
{
    constexpr int TOT = H * 64;
    dim3 grid((N_NODES + 127) / 128, (TOT + 127) / 128);
    tf32_gemm_kernel<<<grid, 256>>>(in, W, xp, N_NODES, TOT, F);
    int nw = N_NODES * H;
    sd_kernel<<<(nw * 32 + 255) / 256, 256>>>(xp, asrc, adst, s, d, H, 64);
    gat_aggregate_kernel<H, THREADS, VEC><<<N_NODES, THREADS>>>(
        rowptr, csr, s, d, xp, bias, outbuf);
}

// ---------------------------------------------------------------------------
extern "C" void kernel_launch(void* const* d_in, const int* in_sizes, int n_in,
                              void* d_out, int out_size)
{
    const float* x    = (const float*)d_in[0];
    const int*   ei   = (const int*)  d_in[1];
    const float* W1   = (const float*)d_in[2];
    const float* as1  = (const float*)d_in[3];
    const float* ad1  = (const float*)d_in[4];
    const float* b1   = (const float*)d_in[5];
    const float* W2   = (const float*)d_in[6];
    const float* as2  = (const float*)d_in[7];
    const float* ad2  = (const float*)d_in[8];
    const float* b2   = (const float*)d_in[9];
    const float* W3   = (const float*)d_in[10];
    const float* as3  = (const float*)d_in[11];
    const float* ad3  = (const float*)d_in[12];
    const float* b3   = (const float*)d_in[13];
    const float* Wfc  = (const float*)d_in[14];
    const float* bfc  = (const float*)d_in[15];
    float* out = (float*)d_out;

    float *hbuf, *xp, *s, *d;
    int *deg, *rowptr, *cursor, *csr;
    cudaGetSymbolAddress((void**)&hbuf,   g_h);
    cudaGetSymbolAddress((void**)&xp,     g_xp);
    cudaGetSymbolAddress((void**)&s,      g_s);
    cudaGetSymbolAddress((void**)&d,      g_d);
    cudaGetSymbolAddress((void**)&deg,    g_deg);
    cudaGetSymbolAddress((void**)&rowptr, g_rowptr);
    cudaGetSymbolAddress((void**)&cursor, g_cursor);
    cudaGetSymbolAddress((void**)&csr,    g_csr);

    // ---- CSR build (dst-sorted adjacency, self loop first in each segment) ----
    deg_init_kernel<<<(N_NODES + 255) / 256, 256>>>(deg);
    deg_hist_kernel<<<(N_EDGES + 255) / 256, 256>>>(ei, deg);
    scan_kernel<<<1, 1024>>>(deg, rowptr);
    self_loop_kernel<<<(N_NODES + 255) / 256, 256>>>(rowptr, csr, cursor);
    scatter_kernel<<<(N_EDGES + 255) / 256, 256>>>(ei, cursor, csr);

    // ---- layers ----
    run_gat_layer<4, 64, 4>(x,    128, W1, as1, ad1, b1, rowptr, csr, xp, s, d, hbuf);
    run_gat_layer<4, 64, 4>(hbuf, 256, W2, as2, ad2, b2, rowptr, csr, xp, s, d, hbuf);
    run_gat_layer<1, 32, 2>(hbuf, 256, W3, as3, ad3, b3, rowptr, csr, xp, s, d, hbuf);

    // ---- FC head ----
    fc_kernel<<<(N_NODES * 32 + 255) / 256, 256>>>(hbuf, Wfc, bfc, out);
}

// round 15
// speedup vs baseline: 1.7941x; 1.0430x over previous
#include <cuda_runtime.h>
#include <cstdint>
#include <cstddef>

#define N_NODES   50000
#define N_EDGES   800000
#define E_TOT     850000   // edges + self loops
#define NEG_SLOPE 0.2f

// ---------------------------------------------------------------------------
// Static device scratch (allocation-free)
// ---------------------------------------------------------------------------
static __device__ __align__(256) float g_h  [(size_t)N_NODES * 256];  // layer io
static __device__ __align__(256) float g_xp [(size_t)N_NODES * 256];  // x @ W
static __device__ __align__(256) float g_s  [N_NODES * 4];
static __device__ __align__(256) float g_d  [N_NODES * 4];
static __device__ __align__(256) int   g_deg   [N_NODES];
static __device__ __align__(256) int   g_rowptr[N_NODES + 1];
static __device__ __align__(256) int   g_cursor[N_NODES];
static __device__ __align__(256) int   g_csr   [E_TOT];

// ---------------------------------------------------------------------------
// tf32 helpers (3xTF32 decomposition)
// ---------------------------------------------------------------------------
__device__ __forceinline__ uint32_t f2tf32(float x) {
    uint32_t r;
    asm("cvt.rna.tf32.f32 %0, %1;" : "=r"(r) : "f"(x));
    return r;
}

__device__ __forceinline__ void decomp(float x, uint32_t& hi, uint32_t& lo) {
    hi = f2tf32(x);
    lo = f2tf32(x - __uint_as_float(hi));
}

__device__ __forceinline__ void mma_tf32(float* c,
                                         uint32_t a0, uint32_t a1, uint32_t a2, uint32_t a3,
                                         uint32_t b0, uint32_t b1) {
    asm volatile("mma.sync.aligned.m16n8k8.row.col.f32.tf32.tf32.f32 "
                 "{%0,%1,%2,%3}, {%4,%5,%6,%7}, {%8,%9}, {%0,%1,%2,%3};"
                 : "+f"(c[0]), "+f"(c[1]), "+f"(c[2]), "+f"(c[3])
                 : "r"(a0), "r"(a1), "r"(a2), "r"(a3), "r"(b0), "r"(b1));
}

// ---------------------------------------------------------------------------
// 3xTF32 tensor-core GEMM with fused s/d attention-projection epilogue.
// C[M,N] = A[M,K] @ B[K,N]; s[n,h] += <C[n,head h], asrc[h]>, same for d.
// BM=BN=128, BK=16, 256 threads (8 warps, 64x32 warp tiles). H = N/64.
// ---------------------------------------------------------------------------
__global__ __launch_bounds__(256)
void tf32_gemm_kernel(const float* __restrict__ A, const float* __restrict__ B,
                      float* __restrict__ C, int M, int N, int K,
                      const float* __restrict__ asrc, const float* __restrict__ adst,
                      float* __restrict__ sv, float* __restrict__ dv)
{
    constexpr int BM = 128, BN = 128, BK = 16;
    constexpr int AST = BK + 4;
    constexpr int BST = BN + 8;

    __shared__ uint32_t As[2][BM * AST];
    __shared__ uint32_t Bs[2][BK * BST];

    const int tid  = threadIdx.x;
    const int lane = tid & 31;
    const int wid  = tid >> 5;
    const int gid  = lane >> 2;     // 0..7
    const int tg   = lane & 3;      // 0..3
    const int wm   = (wid & 1) * 64;
    const int wn   = (wid >> 1) * 32;
    const int rowBase = blockIdx.x * BM;
    const int colBase = blockIdx.y * BN;

    const int aR = tid >> 2;
    const int aC = (tid & 3) * 4;
    const int bR = tid >> 5;
    const int bC = (tid & 31) * 4;

    const bool bColOk = (colBase + bC) < N;

    float c[4][4][4];
#pragma unroll
    for (int mi = 0; mi < 4; mi++)
#pragma unroll
        for (int ni = 0; ni < 4; ni++)
#pragma unroll
            for (int f = 0; f < 4; f++) c[mi][ni][f] = 0.f;

    float4 pa0, pa1, pb0, pb1;
    {
        const float4 z = make_float4(0.f, 0.f, 0.f, 0.f);
        pa0 = z; pa1 = z; pb0 = z; pb1 = z;
        int r0 = rowBase + aR, r1 = r0 + 64;
        if (r0 < M) pa0 = *(const float4*)&A[(size_t)r0 * K + aC];
        if (r1 < M) pa1 = *(const float4*)&A[(size_t)r1 * K + aC];
        if (bColOk) {
            pb0 = *(const float4*)&B[(size_t)(bR    ) * N + colBase + bC];
            pb1 = *(const float4*)&B[(size_t)(bR + 8) * N + colBase + bC];
        }
    }

    for (int k0 = 0; k0 < K; k0 += BK) {
        {
            uint32_t h[4], l[4];
            decomp(pa0.x, h[0], l[0]); decomp(pa0.y, h[1], l[1]);
            decomp(pa0.z, h[2], l[2]); decomp(pa0.w, h[3], l[3]);
            *(uint4*)&As[0][aR * AST + aC] = make_uint4(h[0], h[1], h[2], h[3]);
            *(uint4*)&As[1][aR * AST + aC] = make_uint4(l[0], l[1], l[2], l[3]);
            decomp(pa1.x, h[0], l[0]); decomp(pa1.y, h[1], l[1]);
            decomp(pa1.z, h[2], l[2]); decomp(pa1.w, h[3], l[3]);
            *(uint4*)&As[0][(aR + 64) * AST + aC] = make_uint4(h[0], h[1], h[2], h[3]);
            *(uint4*)&As[1][(aR + 64) * AST + aC] = make_uint4(l[0], l[1], l[2], l[3]);
            decomp(pb0.x, h[0], l[0]); decomp(pb0.y, h[1], l[1]);
            decomp(pb0.z, h[2], l[2]); decomp(pb0.w, h[3], l[3]);
            *(uint4*)&Bs[0][bR * BST + bC] = make_uint4(h[0], h[1], h[2], h[3]);
            *(uint4*)&Bs[1][bR * BST + bC] = make_uint4(l[0], l[1], l[2], l[3]);
            decomp(pb1.x, h[0], l[0]); decomp(pb1.y, h[1], l[1]);
            decomp(pb1.z, h[2], l[2]); decomp(pb1.w, h[3], l[3]);
            *(uint4*)&Bs[0][(bR + 8) * BST + bC] = make_uint4(h[0], h[1], h[2], h[3]);
            *(uint4*)&Bs[1][(bR + 8) * BST + bC] = make_uint4(l[0], l[1], l[2], l[3]);
        }
        __syncthreads();

        if (k0 + BK < K) {
            const float4 z = make_float4(0.f, 0.f, 0.f, 0.f);
            pa0 = z; pa1 = z; pb0 = z; pb1 = z;
            int kn = k0 + BK;
            int r0 = rowBase + aR, r1 = r0 + 64;
            if (r0 < M) pa0 = *(const float4*)&A[(size_t)r0 * K + kn + aC];
            if (r1 < M) pa1 = *(const float4*)&A[(size_t)r1 * K + kn + aC];
            if (bColOk) {
                pb0 = *(const float4*)&B[(size_t)(kn + bR    ) * N + colBase + bC];
                pb1 = *(const float4*)&B[(size_t)(kn + bR + 8) * N + colBase + bC];
            }
        }

#pragma unroll
        for (int ks = 0; ks < 2; ks++) {
            const int kb = ks * 8;
            uint32_t bh[4][2], bl[4][2];
#pragma unroll
            for (int ni = 0; ni < 4; ni++) {
                int n = wn + ni * 8 + gid;
                bh[ni][0] = Bs[0][(kb + tg    ) * BST + n];
                bh[ni][1] = Bs[0][(kb + tg + 4) * BST + n];
                bl[ni][0] = Bs[1][(kb + tg    ) * BST + n];
                bl[ni][1] = Bs[1][(kb + tg + 4) * BST + n];
            }
#pragma unroll
            for (int mi = 0; mi < 4; mi++) {
                int m = wm + mi * 16;
                uint32_t ah[4], al[4];
                ah[0] = As[0][(m + gid    ) * AST + kb + tg    ];
                ah[1] = As[0][(m + gid + 8) * AST + kb + tg    ];
                ah[2] = As[0][(m + gid    ) * AST + kb + tg + 4];
                ah[3] = As[0][(m + gid + 8) * AST + kb + tg + 4];
                al[0] = As[1][(m + gid    ) * AST + kb + tg    ];
                al[1] = As[1][(m + gid + 8) * AST + kb + tg    ];
                al[2] = As[1][(m + gid    ) * AST + kb + tg + 4];
                al[3] = As[1][(m + gid + 8) * AST + kb + tg + 4];
#pragma unroll
                for (int ni = 0; ni < 4; ni++) {
                    mma_tf32(c[mi][ni], al[0], al[1], al[2], al[3], bh[ni][0], bh[ni][1]);
                    mma_tf32(c[mi][ni], ah[0], ah[1], ah[2], ah[3], bl[ni][0], bl[ni][1]);
                    mma_tf32(c[mi][ni], ah[0], ah[1], ah[2], ah[3], bh[ni][0], bh[ni][1]);
                }
            }
        }
        __syncthreads();
    }

    // ---- epilogue: store C ----
#pragma unroll
    for (int mi = 0; mi < 4; mi++) {
#pragma unroll
        for (int ni = 0; ni < 4; ni++) {
            int gr0 = rowBase + wm + mi * 16 + gid;
            int gr1 = gr0 + 8;
            int gc  = colBase + wn + ni * 8 + tg * 2;
            if (gc < N) {
                if (gr0 < M)
                    *(float2*)&C[(size_t)gr0 * N + gc] = make_float2(c[mi][ni][0], c[mi][ni][1]);
                if (gr1 < M)
                    *(float2*)&C[(size_t)gr1 * N + gc] = make_float2(c[mi][ni][2], c[mi][ni][3]);
            }
        }
    }

    // ---- fused s/d epilogue: each warp covers 32 cols inside ONE 64-col head ----
    const int colW = colBase + wn;
    if (colW < N) {
        const int H = N >> 6;
        const int h = colW >> 6;
        float srow[8], drow[8];
#pragma unroll
        for (int r = 0; r < 8; r++) { srow[r] = 0.f; drow[r] = 0.f; }
#pragma unroll
        for (int ni = 0; ni < 4; ni++) {
            int cl = (wn + ni * 8 + tg * 2) & 63;
            float as0 = asrc[h * 64 + cl], as1 = asrc[h * 64 + cl + 1];
            float ad0 = adst[h * 64 + cl], ad1 = adst[h * 64 + cl + 1];
#pragma unroll
            for (int mi = 0; mi < 4; mi++) {
                srow[mi*2  ] += c[mi][ni][0]*as0 + c[mi][ni][1]*as1;
                srow[mi*2+1] += c[mi][ni][2]*as0 + c[mi][ni][3]*as1;
                drow[mi*2  ] += c[mi][ni][0]*ad0 + c[mi][ni][1]*ad1;
                drow[mi*2+1] += c[mi][ni][2]*ad0 + c[mi][ni][3]*ad1;
            }
        }
#pragma unroll
        for (int r = 0; r < 8; r++) {
            srow[r] += __shfl_xor_sync(0xffffffffu, srow[r], 1);
            srow[r] += __shfl_xor_sync(0xffffffffu, srow[r], 2);
            drow[r] += __shfl_xor_sync(0xffffffffu, drow[r], 1);
            drow[r] += __shfl_xor_sync(0xffffffffu, drow[r], 2);
        }
        if (tg == 0) {
#pragma unroll
            for (int r = 0; r < 8; r++) {
                int gr = rowBase + wm + (r >> 1) * 16 + gid + (r & 1) * 8;
                if (gr < M) {
                    atomicAdd(&sv[gr * H + h], srow[r]);
                    atomicAdd(&dv[gr * H + h], drow[r]);
                }
            }
        }
    }
}

// ---------------------------------------------------------------------------
// init: deg = 1 (self loop), s/d = 0
// ---------------------------------------------------------------------------
__global__ void deg_init_kernel(int* __restrict__ deg,
                                float* __restrict__ s, float* __restrict__ d, int nh)
{
    int i = blockIdx.x * blockDim.x + threadIdx.x;
    if (i < N_NODES) deg[i] = 1;
    if (i < nh) { s[i] = 0.f; d[i] = 0.f; }
}

__global__ void zero_sd_kernel(float* __restrict__ s, float* __restrict__ d, int nh)
{
    int i = blockIdx.x * blockDim.x + threadIdx.x;
    if (i < nh) { s[i] = 0.f; d[i] = 0.f; }
}

__global__ void deg_hist_kernel(const int* __restrict__ ei, int* __restrict__ deg)
{
    int e = blockIdx.x * blockDim.x + threadIdx.x;
    if (e < N_EDGES) atomicAdd(&deg[ei[N_EDGES + e]], 1);
}

// single-block exclusive scan; also writes self-loop into csr and inits cursor
__global__ __launch_bounds__(1024) void scan_kernel(const int* __restrict__ deg,
                                                    int* __restrict__ rowptr,
                                                    int* __restrict__ csr,
                                                    int* __restrict__ cursor)
{
    __shared__ int wsum[32];
    __shared__ int carry_s;
    const int t = threadIdx.x;
    const int lane = t & 31, wid = t >> 5;
    if (t == 0) carry_s = 0;
    __syncthreads();
    for (int base = 0; base < N_NODES; base += 1024) {
        int i = base + t;
        int v = (i < N_NODES) ? deg[i] : 0;
        int x = v;
#pragma unroll
        for (int o = 1; o < 32; o <<= 1) {
            int y = __shfl_up_sync(0xffffffffu, x, o);
            if (lane >= o) x += y;
        }
        if (lane == 31) wsum[wid] = x;
        int carry = carry_s;
        __syncthreads();
        if (t < 32) {
            int y = wsum[t];
#pragma unroll
            for (int o = 1; o < 32; o <<= 1) {
                int z = __shfl_up_sync(0xffffffffu, y, o);
                if (t >= o) y += z;
            }
            wsum[t] = y;
        }
        __syncthreads();
        int woff = wid ? wsum[wid - 1] : 0;
        if (i < N_NODES) {
            int p = carry + woff + x - v;
            rowptr[i] = p;
            csr[p] = i;          // self loop first (deterministic slot)
            cursor[i] = p + 1;
        }
        int total = wsum[31];
        __syncthreads();
        if (t == 0) carry_s = carry + total;
        __syncthreads();
    }
    if (t == 0) rowptr[N_NODES] = carry_s;
}

__global__ void scatter_kernel(const int* __restrict__ ei,
                               int* __restrict__ cursor, int* __restrict__ csr)
{
    int e = blockIdx.x * blockDim.x + threadIdx.x;
    if (e < N_EDGES) {
        int dst = ei[N_EDGES + e];
        int p = atomicAdd(&cursor[dst], 1);
        csr[p] = ei[e];
    }
}

// ---------------------------------------------------------------------------
// Fused GAT attention + aggregation: one block per dst node.
// THREADS * VEC == H * 64.
// ---------------------------------------------------------------------------
template<int H, int THREADS, int VEC>
__global__ __launch_bounds__(THREADS)
void gat_aggregate_kernel(const int* __restrict__ rowptr, const int* __restrict__ csr,
                          const float* __restrict__ s, const float* __restrict__ dvec,
                          const float* __restrict__ xp, const float* __restrict__ bias,
                          float* __restrict__ out)
{
    constexpr int TOT = H * 64;
    constexpr int CHUNK = THREADS;
    const int dst = blockIdx.x;
    const int t = threadIdx.x;
    const int rs = rowptr[dst], re = rowptr[dst + 1];

    __shared__ float sm_d[H];
    __shared__ float sm_m[H];
    __shared__ float sm_r[H];
    __shared__ float red[THREADS];
    __shared__ int   s_src[CHUNK];
    __shared__ float s_alpha[CHUNK * H];

    if (t < H) sm_d[t] = dvec[dst * H + t];
    __syncthreads();

    const int h = t % H;
    const float dh = sm_d[h];

    float lm = -3.402823466e38f;
    for (int i = rs + t / H; i < re; i += THREADS / H) {
        int src = csr[i];
        float v = s[src * H + h] + dh;
        v = v > 0.f ? v : NEG_SLOPE * v;
        lm = fmaxf(lm, v);
    }
    red[t] = lm;
    __syncthreads();
#pragma unroll
    for (int off = THREADS / 2; off >= H; off >>= 1) {
        if (t < off) red[t] = fmaxf(red[t], red[t + off]);
        __syncthreads();
    }
    if (t < H) sm_m[t] = red[t];
    __syncthreads();
    const float mh = sm_m[h];

    float ls = 0.f;
    for (int i = rs + t / H; i < re; i += THREADS / H) {
        int src = csr[i];
        float v = s[src * H + h] + dh;
        v = v > 0.f ? v : NEG_SLOPE * v;
        ls += __expf(v - mh);
    }
    __syncthreads();
    red[t] = ls;
    __syncthreads();
#pragma unroll
    for (int off = THREADS / 2; off >= H; off >>= 1) {
        if (t < off) red[t] += red[t + off];
        __syncthreads();
    }
    if (t < H) sm_r[t] = __frcp_rn(red[t] + 1e-16f);
    __syncthreads();

    const int myh = (t * VEC) / 64;
    float acc[VEC];
#pragma unroll
    for (int j = 0; j < VEC; j++) acc[j] = 0.f;

    for (int pos = rs; pos < re; pos += CHUNK) {
        const int count = min(CHUNK, re - pos);
        if (t < count) {
            int src = csr[pos + t];
            s_src[t] = src;
#pragma unroll
            for (int hh = 0; hh < H; hh++) {
                float v = s[src * H + hh] + sm_d[hh];
                v = v > 0.f ? v : NEG_SLOPE * v;
                s_alpha[t * H + hh] = __expf(v - sm_m[hh]) * sm_r[hh];
            }
        }
        __syncthreads();
        int e = 0;
        for (; e + 2 <= count; e += 2) {
            float a0 = s_alpha[(e    ) * H + myh];
            float a1 = s_alpha[(e + 1) * H + myh];
            const float* r0 = xp + (size_t)s_src[e    ] * TOT + t * VEC;
            const float* r1 = xp + (size_t)s_src[e + 1] * TOT + t * VEC;
            if (VEC == 4) {
                float4 v0 = *(const float4*)r0;
                float4 v1 = *(const float4*)r1;
                acc[0] = fmaf(a0, v0.x, acc[0]); acc[1] = fmaf(a0, v0.y, acc[1]);
                acc[2] = fmaf(a0, v0.z, acc[2]); acc[3] = fmaf(a0, v0.w, acc[3]);
                acc[0] = fmaf(a1, v1.x, acc[0]); acc[1] = fmaf(a1, v1.y, acc[1]);
                acc[2] = fmaf(a1, v1.z, acc[2]); acc[3] = fmaf(a1, v1.w, acc[3]);
            } else {
                float2 v0 = *(const float2*)r0;
                float2 v1 = *(const float2*)r1;
                acc[0] = fmaf(a0, v0.x, acc[0]); acc[1] = fmaf(a0, v0.y, acc[1]);
                acc[0] = fmaf(a1, v1.x, acc[0]); acc[1] = fmaf(a1, v1.y, acc[1]);
            }
        }
        if (e < count) {
            float a0 = s_alpha[e * H + myh];
            const float* r0 = xp + (size_t)s_src[e] * TOT + t * VEC;
            if (VEC == 4) {
                float4 v0 = *(const float4*)r0;
                acc[0] = fmaf(a0, v0.x, acc[0]); acc[1] = fmaf(a0, v0.y, acc[1]);
                acc[2] = fmaf(a0, v0.z, acc[2]); acc[3] = fmaf(a0, v0.w, acc[3]);
            } else {
                float2 v0 = *(const float2*)r0;
                acc[0] = fmaf(a0, v0.x, acc[0]); acc[1] = fmaf(a0, v0.y, acc[1]);
            }
        }
        __syncthreads();
    }

#pragma unroll
    for (int j = 0; j < VEC; j++) {
        int c = t * VEC + j;
        out[(size_t)dst * TOT + c] = fmaxf(acc[j] + bias[c], 0.f);
    }
}

// ---------------------------------------------------------------------------
// FC: out[n,k] = sum_c h[n,c]*Wfc[c,k] + bfc[k]; one warp per node
// ---------------------------------------------------------------------------
__global__ void fc_kernel(const float* __restrict__ h, const float* __restrict__ Wfc,
                          const float* __restrict__ bfc, float* __restrict__ out)
{
    int wid  = (blockIdx.x * blockDim.x + threadIdx.x) >> 5;
    int lane = threadIdx.x & 31;
    if (wid >= N_NODES) return;
    float h0 = h[(size_t)wid * 64 + lane];
    float h1 = h[(size_t)wid * 64 + 32 + lane];
#pragma unroll
    for (int k = 0; k < 10; k++) {
        float p = fmaf(h0, Wfc[lane * 10 + k], h1 * Wfc[(lane + 32) * 10 + k]);
#pragma unroll
        for (int o = 16; o; o >>= 1) p += __shfl_down_sync(0xffffffffu, p, o);
        if (lane == 0) out[(size_t)wid * 10 + k] = p + bfc[k];
    }
}

// ---------------------------------------------------------------------------
extern "C" void kernel_launch(void* const* d_in, const int* in_sizes, int n_in,
                              void* d_out, int out_size)
{
    const float* x    = (const float*)d_in[0];
    const int*   ei   = (const int*)  d_in[1];
    const float* W1   = (const float*)d_in[2];
    const float* as1  = (const float*)d_in[3];
    const float* ad1  = (const float*)d_in[4];
    const float* b1   = (const float*)d_in[5];
    const float* W2   = (const float*)d_in[6];
    const float* as2  = (const float*)d_in[7];
    const float* ad2  = (const float*)d_in[8];
    const float* b2   = (const float*)d_in[9];
    const float* W3   = (const float*)d_in[10];
    const float* as3  = (const float*)d_in[11];
    const float* ad3  = (const float*)d_in[12];
    const float* b3   = (const float*)d_in[13];
    const float* Wfc  = (const float*)d_in[14];
    const float* bfc  = (const float*)d_in[15];
    float* out = (float*)d_out;

    float *hbuf, *xp, *s, *d;
    int *deg, *rowptr, *cursor, *csr;
    cudaGetSymbolAddress((void**)&hbuf,   g_h);
    cudaGetSymbolAddress((void**)&xp,     g_xp);
    cudaGetSymbolAddress((void**)&s,      g_s);
    cudaGetSymbolAddress((void**)&d,      g_d);
    cudaGetSymbolAddress((void**)&deg,    g_deg);
    cudaGetSymbolAddress((void**)&rowptr, g_rowptr);
    cudaGetSymbolAddress((void**)&cursor, g_cursor);
    cudaGetSymbolAddress((void**)&csr,    g_csr);

    dim3 g1((N_NODES + 127) / 128, 2);   // layers 1/2: N=256
    dim3 g3((N_NODES + 127) / 128, 1);   // layer 3:   N=64

    // (1) init: deg=1, s/d=0
    deg_init_kernel<<<(N_NODES * 4 + 255) / 256, 256>>>(deg, s, d, N_NODES * 4);
    // (2) degree histogram
    deg_hist_kernel<<<(N_EDGES + 255) / 256, 256>>>(ei, deg);
    // (3) scan + self-loop + cursor init
    scan_kernel<<<1, 1024>>>(deg, rowptr, csr, cursor);
    // (4) layer-1 GEMM + fused s/d  <-- ncu capture slot
    tf32_gemm_kernel<<<g1, 256>>>(x, W1, xp, N_NODES, 256, 128, as1, ad1, s, d);
    // (5) CSR scatter
    scatter_kernel<<<(N_EDGES + 255) / 256, 256>>>(ei, cursor, csr);
    // (6) layer-1 aggregate
    gat_aggregate_kernel<4, 64, 4><<<N_NODES, 64>>>(rowptr, csr, s, d, xp, b1, hbuf);
    // (7..9) layer 2
    zero_sd_kernel<<<(N_NODES * 4 + 255) / 256, 256>>>(s, d, N_NODES * 4);
    tf32_gemm_kernel<<<g1, 256>>>(hbuf, W2, xp, N_NODES, 256, 256, as2, ad2, s, d);
    gat_aggregate_kernel<4, 64, 4><<<N_NODES, 64>>>(rowptr, csr, s, d, xp, b2, hbuf);
    // (10..12) layer 3
    zero_sd_kernel<<<(N_NODES + 255) / 256, 256>>>(s, d, N_NODES);
    tf32_gemm_kernel<<<g3, 256>>>(hbuf, W3, xp, N_NODES, 64, 256, as3, ad3, s, d);
    gat_aggregate_kernel<1, 32, 2><<<N_NODES, 32>>>(rowptr, csr, s, d, xp, b3, hbuf);
    // (13) FC head
    fc_kernel<<<(N_NODES * 32 + 255) / 256, 256>>>(hbuf, Wfc, bfc, out);
}